// round 2
// baseline (speedup 1.0000x reference)
#include <cuda_runtime.h>

// PolynomialADMRSolver — B=4096, N=32, D=1024, fp32.
// out[b,d] = mean_k( x^e_k ), e={2,3,5,7}, x = states[b,d]*(sum_n w[b,n]*nb[b,n,d] + valence[b])
//
// R2: persistent grid-stride (grid = 148*8 exactly one full wave), no smem/no
// __syncthreads (weights via uniform __ldg broadcast), __ldcs streaming loads
// on the 512 MiB neighbor stream. Pure HBM-bound; target ~90% of 8 TB/s.

static constexpr int B = 4096;
static constexpr int N = 32;
static constexpr int D = 1024;
static constexpr int THREADS = 256;          // D/4 float4 lanes
static constexpr int SMS = 148;
static constexpr int CTAS_PER_SM = 8;        // 256 thr * 8 = 2048 thr/SM
static constexpr int GRID = SMS * CTAS_PER_SM;   // 1184 — one full wave

__global__ __launch_bounds__(THREADS)
void poly_admr_kernel(const float* __restrict__ states,
                      const float* __restrict__ neighbor_states,
                      const float* __restrict__ adjacency_weight,
                      const float* __restrict__ valence,
                      float* __restrict__ out)
{
    const int t = threadIdx.x;

    for (int b = blockIdx.x; b < B; b += GRID) {
        const float4* __restrict__ nb = reinterpret_cast<const float4*>(
            neighbor_states + (size_t)b * N * D);
        const float* __restrict__ wrow = adjacency_weight + (size_t)b * N;

        float4 acc = make_float4(0.f, 0.f, 0.f, 0.f);

        // 4 batches of 8 independent float4 streaming loads (MLP=8/thread).
        #pragma unroll
        for (int n0 = 0; n0 < N; n0 += 8) {
            float4 x[8];
            #pragma unroll
            for (int i = 0; i < 8; ++i)
                x[i] = __ldcs(&nb[(size_t)(n0 + i) * THREADS + t]);

            #pragma unroll
            for (int i = 0; i < 8; ++i) {
                const float wn = __ldg(&wrow[n0 + i]);  // warp-uniform, L1-hit
                acc.x = fmaf(wn, x[i].x, acc.x);
                acc.y = fmaf(wn, x[i].y, acc.y);
                acc.z = fmaf(wn, x[i].z, acc.z);
                acc.w = fmaf(wn, x[i].w, acc.w);
            }
        }

        const float v = __ldg(&valence[b]);
        const float4 s = __ldg(&reinterpret_cast<const float4*>(
            states + (size_t)b * D)[t]);

        float4 r;
        {
            float x = s.x * (acc.x + v);
            float x2 = x * x, x3 = x2 * x, x5 = x3 * x2, x7 = x5 * x2;
            r.x = 0.25f * (x2 + x3 + x5 + x7);
        }
        {
            float x = s.y * (acc.y + v);
            float x2 = x * x, x3 = x2 * x, x5 = x3 * x2, x7 = x5 * x2;
            r.y = 0.25f * (x2 + x3 + x5 + x7);
        }
        {
            float x = s.z * (acc.z + v);
            float x2 = x * x, x3 = x2 * x, x5 = x3 * x2, x7 = x5 * x2;
            r.z = 0.25f * (x2 + x3 + x5 + x7);
        }
        {
            float x = s.w * (acc.w + v);
            float x2 = x * x, x3 = x2 * x, x5 = x3 * x2, x7 = x5 * x2;
            r.w = 0.25f * (x2 + x3 + x5 + x7);
        }

        __stcs(&reinterpret_cast<float4*>(out + (size_t)b * D)[t], r);
    }
}

extern "C" void kernel_launch(void* const* d_in, const int* in_sizes, int n_in,
                              void* d_out, int out_size)
{
    const float* states            = (const float*)d_in[0];
    const float* neighbor_states   = (const float*)d_in[1];
    const float* adjacency_weight  = (const float*)d_in[2];
    const float* valence           = (const float*)d_in[3];
    float* out = (float*)d_out;

    poly_admr_kernel<<<GRID, THREADS>>>(states, neighbor_states,
                                        adjacency_weight, valence, out);
}

// round 3
// speedup vs baseline: 1.0124x; 1.0124x over previous
#include <cuda_runtime.h>

// PolynomialADMRSolver — B=4096, N=32, D=1024, fp32.
// out[b,d] = mean_k( x^e_k ), e={2,3,5,7}, x = states[b,d]*(sum_n w[b,n]*nb[b,n,d] + valence[b])
//
// R3: single change vs R1 — __launch_bounds__(256, 4) lifts the ptxas register
// target from 32 to 64 regs/thread so the 8-deep float4 load batch actually
// stays in flight (true MLP=8/thread). One CTA per b, grid=4096, plain LDG
// (R1's plain-load variant outperformed __ldcs), weights via warp-uniform __ldg.

static constexpr int B = 4096;
static constexpr int N = 32;
static constexpr int D = 1024;
static constexpr int THREADS = 256;          // D/4 float4 lanes

__global__ __launch_bounds__(THREADS, 4)     // 64 regs/thread budget
void poly_admr_kernel(const float* __restrict__ states,
                      const float* __restrict__ neighbor_states,
                      const float* __restrict__ adjacency_weight,
                      const float* __restrict__ valence,
                      float* __restrict__ out)
{
    const int b = blockIdx.x;
    const int t = threadIdx.x;

    const float4* __restrict__ nb = reinterpret_cast<const float4*>(
        neighbor_states + (size_t)b * N * D);
    const float* __restrict__ wrow = adjacency_weight + (size_t)b * N;

    float4 acc = make_float4(0.f, 0.f, 0.f, 0.f);

    // 4 batches of 8 independent float4 loads, front-batched (MLP_p1 = 8).
    #pragma unroll
    for (int n0 = 0; n0 < N; n0 += 8) {
        float4 x[8];
        #pragma unroll
        for (int i = 0; i < 8; ++i)
            x[i] = nb[(size_t)(n0 + i) * THREADS + t];

        #pragma unroll
        for (int i = 0; i < 8; ++i) {
            const float wn = __ldg(&wrow[n0 + i]);   // warp-uniform, L1-hit
            acc.x = fmaf(wn, x[i].x, acc.x);
            acc.y = fmaf(wn, x[i].y, acc.y);
            acc.z = fmaf(wn, x[i].z, acc.z);
            acc.w = fmaf(wn, x[i].w, acc.w);
        }
    }

    const float v = __ldg(&valence[b]);
    const float4 s = reinterpret_cast<const float4*>(states + (size_t)b * D)[t];

    float4 r;
    {
        float x = s.x * (acc.x + v);
        float x2 = x * x, x3 = x2 * x, x5 = x3 * x2, x7 = x5 * x2;
        r.x = 0.25f * (x2 + x3 + x5 + x7);
    }
    {
        float x = s.y * (acc.y + v);
        float x2 = x * x, x3 = x2 * x, x5 = x3 * x2, x7 = x5 * x2;
        r.y = 0.25f * (x2 + x3 + x5 + x7);
    }
    {
        float x = s.z * (acc.z + v);
        float x2 = x * x, x3 = x2 * x, x5 = x3 * x2, x7 = x5 * x2;
        r.z = 0.25f * (x2 + x3 + x5 + x7);
    }
    {
        float x = s.w * (acc.w + v);
        float x2 = x * x, x3 = x2 * x, x5 = x3 * x2, x7 = x5 * x2;
        r.w = 0.25f * (x2 + x3 + x5 + x7);
    }

    reinterpret_cast<float4*>(out + (size_t)b * D)[t] = r;
}

extern "C" void kernel_launch(void* const* d_in, const int* in_sizes, int n_in,
                              void* d_out, int out_size)
{
    const float* states            = (const float*)d_in[0];
    const float* neighbor_states   = (const float*)d_in[1];
    const float* adjacency_weight  = (const float*)d_in[2];
    const float* valence           = (const float*)d_in[3];
    float* out = (float*)d_out;

    poly_admr_kernel<<<B, THREADS>>>(states, neighbor_states,
                                     adjacency_weight, valence, out);
}

// round 4
// speedup vs baseline: 1.0215x; 1.0091x over previous
#include <cuda_runtime.h>

// PolynomialADMRSolver — B=4096, N=32, D=1024, fp32.
// out[b,d] = mean_k( x^e_k ), e={2,3,5,7}, x = states[b,d]*(sum_n w[b,n]*nb[b,n,d] + valence[b])
//
// R4: single change vs R3 — load-batch depth 8 -> 16 (2 batches cover N=32),
// paid for with __launch_bounds__(256, 3) (~84 regs/thread). Keeps the DRAM
// request queue full across the whole mainloop instead of draining between
// 8-deep batches. One CTA per b, grid=4096.

static constexpr int B = 4096;
static constexpr int N = 32;
static constexpr int D = 1024;
static constexpr int THREADS = 256;          // D/4 float4 lanes
static constexpr int BATCH = 16;             // float4 loads in flight per thread

__global__ __launch_bounds__(THREADS, 3)     // ~84 regs/thread budget
void poly_admr_kernel(const float* __restrict__ states,
                      const float* __restrict__ neighbor_states,
                      const float* __restrict__ adjacency_weight,
                      const float* __restrict__ valence,
                      float* __restrict__ out)
{
    const int b = blockIdx.x;
    const int t = threadIdx.x;

    const float4* __restrict__ nb = reinterpret_cast<const float4*>(
        neighbor_states + (size_t)b * N * D);
    const float* __restrict__ wrow = adjacency_weight + (size_t)b * N;

    float4 acc = make_float4(0.f, 0.f, 0.f, 0.f);

    #pragma unroll
    for (int n0 = 0; n0 < N; n0 += BATCH) {
        float4 x[BATCH];
        #pragma unroll
        for (int i = 0; i < BATCH; ++i)
            x[i] = nb[(size_t)(n0 + i) * THREADS + t];

        #pragma unroll
        for (int i = 0; i < BATCH; ++i) {
            const float wn = __ldg(&wrow[n0 + i]);   // warp-uniform, L1-hit
            acc.x = fmaf(wn, x[i].x, acc.x);
            acc.y = fmaf(wn, x[i].y, acc.y);
            acc.z = fmaf(wn, x[i].z, acc.z);
            acc.w = fmaf(wn, x[i].w, acc.w);
        }
    }

    const float v = __ldg(&valence[b]);
    const float4 s = reinterpret_cast<const float4*>(states + (size_t)b * D)[t];

    float4 r;
    {
        float x = s.x * (acc.x + v);
        float x2 = x * x, x3 = x2 * x, x5 = x3 * x2, x7 = x5 * x2;
        r.x = 0.25f * (x2 + x3 + x5 + x7);
    }
    {
        float x = s.y * (acc.y + v);
        float x2 = x * x, x3 = x2 * x, x5 = x3 * x2, x7 = x5 * x2;
        r.y = 0.25f * (x2 + x3 + x5 + x7);
    }
    {
        float x = s.z * (acc.z + v);
        float x2 = x * x, x3 = x2 * x, x5 = x3 * x2, x7 = x5 * x2;
        r.z = 0.25f * (x2 + x3 + x5 + x7);
    }
    {
        float x = s.w * (acc.w + v);
        float x2 = x * x, x3 = x2 * x, x5 = x3 * x2, x7 = x5 * x2;
        r.w = 0.25f * (x2 + x3 + x5 + x7);
    }

    reinterpret_cast<float4*>(out + (size_t)b * D)[t] = r;
}

extern "C" void kernel_launch(void* const* d_in, const int* in_sizes, int n_in,
                              void* d_out, int out_size)
{
    const float* states            = (const float*)d_in[0];
    const float* neighbor_states   = (const float*)d_in[1];
    const float* adjacency_weight  = (const float*)d_in[2];
    const float* valence           = (const float*)d_in[3];
    float* out = (float*)d_out;

    poly_admr_kernel<<<B, THREADS>>>(states, neighbor_states,
                                     adjacency_weight, valence, out);
}

// round 6
// speedup vs baseline: 1.0246x; 1.0030x over previous
#include <cuda_runtime.h>

// PolynomialADMRSolver — B=4096, N=32, D=1024, fp32.
// out[b,d] = mean_k( x^e_k ), e={2,3,5,7}, x = states[b,d]*(sum_n w[b,n]*nb[b,n,d] + valence[b])
//
// R6: explicit 4-stage software pipeline (ping-pong depth 8), fully unrolled
// and bounds-exact (fixes R5's OOB prefetch). Loads issue continuously across
// the whole mainloop. One CTA per b, grid=4096, __launch_bounds__(256,3).

static constexpr int B = 4096;
static constexpr int N = 32;
static constexpr int D = 1024;
static constexpr int THREADS = 256;          // D/4 float4 lanes
static constexpr int PIPE = 8;

__global__ __launch_bounds__(THREADS, 3)
void poly_admr_kernel(const float* __restrict__ states,
                      const float* __restrict__ neighbor_states,
                      const float* __restrict__ adjacency_weight,
                      const float* __restrict__ valence,
                      float* __restrict__ out)
{
    const int b = blockIdx.x;
    const int t = threadIdx.x;

    const float4* __restrict__ nb = reinterpret_cast<const float4*>(
        neighbor_states + (size_t)b * N * D);
    const float* __restrict__ wrow = adjacency_weight + (size_t)b * N;

    // Hoisted: overlap these latencies with the neighbor stream.
    const float v = __ldg(&valence[b]);
    const float4 s = reinterpret_cast<const float4*>(states + (size_t)b * D)[t];

    float4 acc = make_float4(0.f, 0.f, 0.f, 0.f);
    float4 xa[PIPE], xb[PIPE];

    #define LOAD_BATCH(buf, base)                                   \
        _Pragma("unroll")                                           \
        for (int i = 0; i < PIPE; ++i)                              \
            buf[i] = nb[(size_t)((base) + i) * THREADS + t];

    #define FMA_BATCH(buf, base)                                    \
        _Pragma("unroll")                                           \
        for (int i = 0; i < PIPE; ++i) {                            \
            const float wn = __ldg(&wrow[(base) + i]);              \
            acc.x = fmaf(wn, buf[i].x, acc.x);                      \
            acc.y = fmaf(wn, buf[i].y, acc.y);                      \
            acc.z = fmaf(wn, buf[i].z, acc.z);                      \
            acc.w = fmaf(wn, buf[i].w, acc.w);                      \
        }

    LOAD_BATCH(xa, 0)                     // batch 0 in flight
    LOAD_BATCH(xb, 8)   FMA_BATCH(xa, 0)  // batch 1 in flight while consuming 0
    LOAD_BATCH(xa, 16)  FMA_BATCH(xb, 8)  // batch 2 in flight while consuming 1
    LOAD_BATCH(xb, 24)  FMA_BATCH(xa, 16) // batch 3 in flight while consuming 2
    FMA_BATCH(xb, 24)                     // consume batch 3 — no further loads

    #undef LOAD_BATCH
    #undef FMA_BATCH

    float4 r;
    {
        float x = s.x * (acc.x + v);
        float x2 = x * x, x3 = x2 * x, x5 = x3 * x2, x7 = x5 * x2;
        r.x = 0.25f * (x2 + x3 + x5 + x7);
    }
    {
        float x = s.y * (acc.y + v);
        float x2 = x * x, x3 = x2 * x, x5 = x3 * x2, x7 = x5 * x2;
        r.y = 0.25f * (x2 + x3 + x5 + x7);
    }
    {
        float x = s.z * (acc.z + v);
        float x2 = x * x, x3 = x2 * x, x5 = x3 * x2, x7 = x5 * x2;
        r.z = 0.25f * (x2 + x3 + x5 + x7);
    }
    {
        float x = s.w * (acc.w + v);
        float x2 = x * x, x3 = x2 * x, x5 = x3 * x2, x7 = x5 * x2;
        r.w = 0.25f * (x2 + x3 + x5 + x7);
    }

    reinterpret_cast<float4*>(out + (size_t)b * D)[t] = r;
}

extern "C" void kernel_launch(void* const* d_in, const int* in_sizes, int n_in,
                              void* d_out, int out_size)
{
    const float* states            = (const float*)d_in[0];
    const float* neighbor_states   = (const float*)d_in[1];
    const float* adjacency_weight  = (const float*)d_in[2];
    const float* valence           = (const float*)d_in[3];
    float* out = (float*)d_out;

    poly_admr_kernel<<<B, THREADS>>>(states, neighbor_states,
                                     adjacency_weight, valence, out);
}